// round 10
// baseline (speedup 1.0000x reference)
#include <cuda_runtime.h>

// ---------------------------------------------------------------------------
// Inverse DTCWT, 2 levels.
//   k1: level-1 vertical qshift (2 k-groups/thread) -> g_Y1/g_Y2
//   k2: level-1 horizontal qshift (vectorized) -> g_Z
//   kB: level-0 biort fused tiled, hi0 smem-staged in 2 halves -> out
// ---------------------------------------------------------------------------

#define SCQ 0.70710678118654752f

__constant__ float cF0[4][7] = {
  { 0.00325314f,  0.03466035f, -0.11720389f,  0.75614564f,  0.01186609f,  0.02382538f, -0.00543948f},
  {-0.00455690f,  0.01702522f, -0.10671180f,  0.56881042f,  0.27529538f, -0.03887280f, -0.00388321f},
  {-0.00388321f, -0.03887280f,  0.27529538f,  0.56881042f, -0.10671180f,  0.01702522f, -0.00455690f},
  {-0.00543948f,  0.02382538f,  0.01186609f,  0.75614564f, -0.11720389f,  0.03466035f,  0.00325314f}
};
__constant__ float cF1[4][7] = {
  {-0.00455690f,  0.01702522f, -0.10671180f,  0.56881042f,  0.27529538f, -0.03887280f, -0.00388321f},
  {-0.00325314f, -0.03466035f,  0.11720389f, -0.75614564f, -0.01186609f, -0.02382538f,  0.00543948f},
  { 0.00543948f, -0.02382538f, -0.01186609f, -0.75614564f,  0.11720389f, -0.03466035f, -0.00325314f},
  {-0.00388321f, -0.03887280f,  0.27529538f,  0.56881042f, -0.10671180f,  0.01702522f, -0.00455690f}
};
__constant__ float cG0[7] = {-0.0107142857142857f, -0.0535714285714286f, 0.2607142857142857f,
                              0.6071428571428571f,  0.2607142857142857f, -0.0535714285714286f,
                             -0.0107142857142857f};
__constant__ float cG1[5] = {-0.05f, -0.25f, 0.6f, -0.25f, -0.05f};

// scratch
__device__ float g_Y1[8 * 512 * 256 * 3];
__device__ float g_Y2[8 * 512 * 256 * 3];
__device__ float g_Z [8 * 512 * 512 * 3];

__device__ __forceinline__ int refl(int p, int L) {
  return p < 0 ? (-1 - p) : (p >= L ? (2 * L - 1 - p) : p);
}
__device__ __forceinline__ float comb(float x, float y, int rp, int wp) {
  return rp == 0 ? (x + y) : (wp == 0 ? (x - y) : (y - x));
}

// ---------------- K1: level-1 vertical qshift, 2 k-groups (8 rows)/thread ---
__global__ __launch_bounds__(256) void k1_lvl1_vert(const float* __restrict__ low,
                                                    const float* __restrict__ hi1) {
  int u = blockIdx.x * 256 + threadIdx.x;   // 0..767 = 3*w+c
  int kp = blockIdx.y;                       // 0..63
  int b = blockIdx.z;
  int w = u / 3, c = u - 3 * w;
  int jj = w >> 1, wp = w & 1;
  const bool interior = (kp >= 2 && kp <= 61);
  const int base = 4 * kp - 6;

  const float* lowb = low + ((b * 256) * 256 + w) * 3 + c;
  const float* hb   = hi1 + ((b * 128) * 128 + jj) * 36 + c;

  int pv[16];
#pragma unroll
  for (int v = 0; v < 16; v++) {
    int p = base + v;
    pv[v] = interior ? p : refl(p, 256);
  }

  float a[8], hl[8];
  {
    float xl[16], xB[16];
#pragma unroll
    for (int v = 0; v < 16; v++) {
      int p = pv[v];
      xl[v] = lowb[p * 768];
      int i = p >> 1, rp = p & 1;
      const float* q = hb + i * 4608 + ((rp ^ wp) ? 18 : 0);
      xB[v] = comb(q[6], q[9], rp, wp);
    }
#pragma unroll
    for (int dk = 0; dk < 2; dk++)
#pragma unroll
      for (int s = 0; s < 4; s++) {
        int v0 = 2 * dk + 12 + (s & 1);
        float aa = 0.f, hh = 0.f;
#pragma unroll
        for (int j = 0; j < 7; j++) {
          float f = cF0[s][j];
          aa += f * xl[v0 - 2 * j];
          hh += f * xB[v0 - 2 * j];
        }
        a[4 * dk + s] = aa; hl[4 * dk + s] = hh;
      }
  }
  {
    float xC[16], xD[16];
#pragma unroll
    for (int v = 0; v < 16; v++) {
      int p = pv[v];
      int i = p >> 1, rp = p & 1;
      const float* q = hb + i * 4608 + ((rp ^ wp) ? 18 : 0);
      xC[v] = comb(q[0], q[15], rp, wp);
      xD[v] = comb(q[3], q[12], rp, wp);
    }
    int ob = ((b * 512 + 8 * kp) * 256 + w) * 3 + c;
#pragma unroll
    for (int dk = 0; dk < 2; dk++)
#pragma unroll
      for (int s = 0; s < 4; s++) {
        int v1 = 2 * dk + 13 - (s & 1);
        float lh = 0.f, hh = 0.f;
#pragma unroll
        for (int j = 0; j < 7; j++) {
          float f = cF1[s][j];
          lh += f * xC[v1 - 2 * j];
          hh += f * xD[v1 - 2 * j];
        }
        int o = ob + (4 * dk + s) * 768;
        g_Y1[o] = a[4 * dk + s] + SCQ * lh;
        g_Y2[o] = SCQ * (hl[4 * dk + s] + hh);
      }
  }
}

// ---------------- K2: level-1 horizontal (qshift over W), vectorized --------
__global__ __launch_bounds__(256, 4) void k2_lvl1_horz() {
  int idx = blockIdx.x * 256 + threadIdx.x;
  int k = idx & 127;
  int h = (idx >> 7) & 511;
  int b = idx >> 16;
  const bool interior = (k >= 3 && k <= 124);
  int rb  = ((b * 512 + h) * 256) * 3;
  int rb2 = ((b * 512 + h) * 512) * 3;

  float O[12];
#pragma unroll
  for (int i = 0; i < 12; i++) O[i] = 0.f;

  {
    float X1[42];
    if (interior) {
      const float2* p2 = (const float2*)(g_Y1 + rb + 6 * k - 18);
#pragma unroll
      for (int m = 0; m < 21; m++) ((float2*)X1)[m] = p2[m];
    } else {
#pragma unroll
      for (int v = 0; v < 14; v++) {
        int pr = refl(2 * k - 6 + v, 256);
#pragma unroll
        for (int c = 0; c < 3; c++) X1[v * 3 + c] = g_Y1[rb + pr * 3 + c];
      }
    }
#pragma unroll
    for (int s = 0; s < 4; s++) {
      int v0 = 12 + (s & 1);
#pragma unroll
      for (int j = 0; j < 7; j++) {
        float f = cF0[s][j];
#pragma unroll
        for (int c = 0; c < 3; c++) O[s * 3 + c] += f * X1[(v0 - 2 * j) * 3 + c];
      }
    }
  }
  {
    float X2[42];
    if (interior) {
      const float2* p2 = (const float2*)(g_Y2 + rb + 6 * k - 18);
#pragma unroll
      for (int m = 0; m < 21; m++) ((float2*)X2)[m] = p2[m];
    } else {
#pragma unroll
      for (int v = 0; v < 14; v++) {
        int pr = refl(2 * k - 6 + v, 256);
#pragma unroll
        for (int c = 0; c < 3; c++) X2[v * 3 + c] = g_Y2[rb + pr * 3 + c];
      }
    }
#pragma unroll
    for (int s = 0; s < 4; s++) {
      int v1 = 13 - (s & 1);
#pragma unroll
      for (int j = 0; j < 7; j++) {
        float f = cF1[s][j];
#pragma unroll
        for (int c = 0; c < 3; c++) O[s * 3 + c] += f * X2[(v1 - 2 * j) * 3 + c];
      }
    }
  }
  float4* po = (float4*)(g_Z + rb2 + 12 * k);
#pragma unroll
  for (int m = 0; m < 3; m++)
    po[m] = make_float4(O[4 * m], O[4 * m + 1], O[4 * m + 2], O[4 * m + 3]);
}

// ---------------- KB: level-0 fused, hi0 staged in smem (2 halves) ----------
// grid (8, 64, 8); block 256. Tile: 8 out rows x 64 out cols.
// hi0 cells needed: rows i0..i0+7, cols jj0..jj0+35 (clamped); staged 4 rows/half.
__global__ __launch_bounds__(256) void kB_lvl0(const float* __restrict__ hi0,
                                               float* __restrict__ out) {
  __shared__ float sS[4 * 1296];        // 4 cell-rows x 36 cells x 36 ch
  __shared__ float sY1[8][210];
  __shared__ float sY2[8][210];
  int wt = blockIdx.x * 64;
  int rt = blockIdx.y * 8;
  int b  = blockIdx.z;
  int t  = threadIdx.x;
  int i0  = (rt >> 1) - 2;
  int jj0 = (wt >> 1) - 2;
  const float* hbase = hi0 + b * 2359296;    // 256*256*36

  int ucol = t / 3, c = t - 3 * ucol;
  int w  = wt - 3 + ucol;
  int wr = refl(w, 512);
  int jjL = (wr >> 1) - jj0;                 // 0..35
  int wp  = wr & 1;
  const bool vint   = (rt >= 4 && rt <= 500);
  const bool active = (t < 210);

  // ---- Z vertical filter (global, coalesced) ----
  float a1[8];
  if (active) {
    const float* zb = g_Z + ((b * 512) * 512 + wr) * 3 + c;
    float xz[14];
#pragma unroll
    for (int v = 0; v < 14; v++) {
      int p = rt - 3 + v;
      int pr = vint ? p : refl(p, 512);
      xz[v] = zb[pr * 1536];
    }
#pragma unroll
    for (int s = 0; s < 8; s++) {
      float acc = 0.f;
#pragma unroll
      for (int j = 0; j < 7; j++) acc += cG0[j] * xz[s + 6 - j];
      a1[s] = acc;
    }
  }

  // ---- hi0 windows via 2-half smem staging ----
  float xhl[14], xlh[12], xhh[12];
#pragma unroll
  for (int H = 0; H < 2; H++) {
    __syncthreads();                         // protect previous half before restage
#pragma unroll
    for (int r = 0; r < 4; r++) {
      int ir = i0 + 4 * H + r;
      ir = ir < 0 ? 0 : (ir > 255 ? 255 : ir);
      const float* src = hbase + ir * 9216;  // 256*36
      for (int e = t; e < 1296; e += 256) {
        int q = e / 36, f = e - 36 * q;
        int jc = jj0 + q; jc = jc < 0 ? 0 : (jc > 255 ? 255 : jc);
        sS[r * 1296 + e] = src[jc * 36 + f];
      }
    }
    __syncthreads();
    if (active) {
      const float* sc = sS + jjL * 36 + c;
      if (vint) {
        // interior: slot(v) = (v+1)>>1 (G0), (v2+2)>>1 (G1) — compile-time split
#pragma unroll
        for (int v = 0; v < 14; v++) {
          int slot = (v + 1) >> 1;
          if ((slot >> 2) == H) {
            int rp = (rt - 3 + v) & 1;
            const float* qq = sc + (slot & 3) * 1296 + ((rp ^ wp) ? 18 : 0);
            xhl[v] = comb(qq[6], qq[9], rp, wp);
          }
        }
#pragma unroll
        for (int v2 = 0; v2 < 12; v2++) {
          int slot = (v2 + 2) >> 1;
          if ((slot >> 2) == H) {
            int rp = (rt - 2 + v2) & 1;
            const float* qq = sc + (slot & 3) * 1296 + ((rp ^ wp) ? 18 : 0);
            xlh[v2] = comb(qq[0], qq[15], rp, wp);
            xhh[v2] = comb(qq[3], qq[12], rp, wp);
          }
        }
      } else {
#pragma unroll
        for (int v = 0; v < 14; v++) {
          int pr = refl(rt - 3 + v, 512);
          int slot = (pr >> 1) - i0;
          if ((slot >> 2) == H) {
            int rp = pr & 1;
            const float* qq = sc + (slot & 3) * 1296 + ((rp ^ wp) ? 18 : 0);
            xhl[v] = comb(qq[6], qq[9], rp, wp);
          }
        }
#pragma unroll
        for (int v2 = 0; v2 < 12; v2++) {
          int pr = refl(rt - 2 + v2, 512);
          int slot = (pr >> 1) - i0;
          if ((slot >> 2) == H) {
            int rp = pr & 1;
            const float* qq = sc + (slot & 3) * 1296 + ((rp ^ wp) ? 18 : 0);
            xlh[v2] = comb(qq[0], qq[15], rp, wp);
            xhh[v2] = comb(qq[3], qq[12], rp, wp);
          }
        }
      }
    }
  }

  // ---- dense vertical accumulation -> sY ----
  if (active) {
#pragma unroll
    for (int s = 0; s < 8; s++) {
      float hl = 0.f, lh = 0.f, hh = 0.f;
#pragma unroll
      for (int j = 0; j < 7; j++) hl += cG0[j] * xhl[s + 6 - j];
#pragma unroll
      for (int j = 0; j < 5; j++) {
        lh += cG1[j] * xlh[s + 4 - j];
        hh += cG1[j] * xhh[s + 4 - j];
      }
      sY1[s][t] = a1[s] + SCQ * lh;
      sY2[s][t] = SCQ * (hl + hh);
    }
  }
  __syncthreads();

  // ---- phase 2: horizontal biort from smem -> out ----
  int row = t >> 5, cp = t & 31;
  int cc0 = 2 * cp;
  float o[6];
#pragma unroll
  for (int d = 0; d < 2; d++) {
    int cc = cc0 + d;
#pragma unroll
    for (int ch = 0; ch < 3; ch++) {
      float acc = 0.f;
#pragma unroll
      for (int j = 0; j < 7; j++) acc += cG0[j] * sY1[row][(cc + 6 - j) * 3 + ch];
#pragma unroll
      for (int j = 0; j < 5; j++) acc += cG1[j] * sY2[row][(cc + 5 - j) * 3 + ch];
      o[d * 3 + ch] = acc;
    }
  }
  int ob = ((b * 512 + rt + row) * 512 + wt + cc0) * 3;
  float2* po = (float2*)(out + ob);
  po[0] = make_float2(o[0], o[1]);
  po[1] = make_float2(o[2], o[3]);
  po[2] = make_float2(o[4], o[5]);
}

extern "C" void kernel_launch(void* const* d_in, const int* in_sizes, int n_in,
                              void* d_out, int out_size) {
  const float *low = nullptr, *high0 = nullptr, *high1 = nullptr;
  for (int i = 0; i < n_in; i++) {
    if (in_sizes[i] == 8 * 256 * 256 * 3)       low   = (const float*)d_in[i];
    else if (in_sizes[i] == 8 * 256 * 256 * 36) high0 = (const float*)d_in[i];
    else if (in_sizes[i] == 8 * 128 * 128 * 36) high1 = (const float*)d_in[i];
  }
  float* out = (float*)d_out;

  k1_lvl1_vert<<<dim3(3, 64, 8), 256>>>(low, high1);
  k2_lvl1_horz<<<2048, 256>>>();
  kB_lvl0<<<dim3(8, 64, 8), 256>>>(high0, out);
}

// round 11
// speedup vs baseline: 2.5723x; 2.5723x over previous
#include <cuda_runtime.h>

// ---------------------------------------------------------------------------
// Inverse DTCWT, 2 levels.
//   kA: level-1 fused (vertical qshift direct-gather -> smem -> horizontal) -> g_Z
//   kB: level-0 biort fused tiled (R8 proven version) -> out
// ---------------------------------------------------------------------------

#define SCQ 0.70710678118654752f

__constant__ float cF0[4][7] = {
  { 0.00325314f,  0.03466035f, -0.11720389f,  0.75614564f,  0.01186609f,  0.02382538f, -0.00543948f},
  {-0.00455690f,  0.01702522f, -0.10671180f,  0.56881042f,  0.27529538f, -0.03887280f, -0.00388321f},
  {-0.00388321f, -0.03887280f,  0.27529538f,  0.56881042f, -0.10671180f,  0.01702522f, -0.00455690f},
  {-0.00543948f,  0.02382538f,  0.01186609f,  0.75614564f, -0.11720389f,  0.03466035f,  0.00325314f}
};
__constant__ float cF1[4][7] = {
  {-0.00455690f,  0.01702522f, -0.10671180f,  0.56881042f,  0.27529538f, -0.03887280f, -0.00388321f},
  {-0.00325314f, -0.03466035f,  0.11720389f, -0.75614564f, -0.01186609f, -0.02382538f,  0.00543948f},
  { 0.00543948f, -0.02382538f, -0.01186609f, -0.75614564f,  0.11720389f, -0.03466035f, -0.00325314f},
  {-0.00388321f, -0.03887280f,  0.27529538f,  0.56881042f, -0.10671180f,  0.01702522f, -0.00455690f}
};
__constant__ float cG0[7] = {-0.0107142857142857f, -0.0535714285714286f, 0.2607142857142857f,
                              0.6071428571428571f,  0.2607142857142857f, -0.0535714285714286f,
                             -0.0107142857142857f};
__constant__ float cG1[5] = {-0.05f, -0.25f, 0.6f, -0.25f, -0.05f};

__device__ float g_Z[8 * 512 * 512 * 3];

__device__ __forceinline__ int refl(int p, int L) {
  return p < 0 ? (-1 - p) : (p >= L ? (2 * L - 1 - p) : p);
}
__device__ __forceinline__ float comb(float x, float y, int rp, int wp) {
  return rp == 0 ? (x + y) : (wp == 0 ? (x - y) : (y - x));
}

// ---------------- kA: level-1 fused, tile = 8 Z-rows x 128 Z-cols -----------
// grid (4, 64, 8), block 256.
// Phase 1: 228 lanes = 76 y-cols x 3 ch, each runs the k1 2-pass vertical
//          (2 k-groups = 8 rows) with direct gmem gathers -> sY1/sY2.
// Phase 2: 256 threads = 8 rows x 32 k-col-groups, horizontal qshift -> g_Z.
__global__ __launch_bounds__(256) void kA_lvl1(const float* __restrict__ low,
                                               const float* __restrict__ hi1) {
  __shared__ float sY1[8][228];
  __shared__ float sY2[8][228];
  int kw0 = blockIdx.x * 32;     // k col-group base (128 Z-cols)
  int kp  = blockIdx.y;          // row-pair index, rows 8kp..8kp+7
  int b   = blockIdx.z;
  int t   = threadIdx.x;

  if (t < 228) {
    int z = t / 3, c = t - 3 * z;          // z: 0..75
    int yc = 2 * kw0 - 6 + z;
    int yr = refl(yc, 256);
    int jj = yr >> 1, wp = yr & 1;
    const bool interior = (kp >= 2 && kp <= 61);
    const int base = 4 * kp - 6;

    const float* lowb = low + ((b * 256) * 256 + yr) * 3 + c;
    const float* hb   = hi1 + ((b * 128) * 128 + jj) * 36 + c;

    int pv[16];
#pragma unroll
    for (int v = 0; v < 16; v++) {
      int p = base + v;
      pv[v] = interior ? p : refl(p, 256);
    }

    float a[8], hl[8];
    // ---- pass A: low + hl streams (F0 taps) ----
    {
      float xl[16], xB[16];
#pragma unroll
      for (int v = 0; v < 16; v++) {
        int p = pv[v];
        xl[v] = lowb[p * 768];
        int i = p >> 1, rp = p & 1;
        const float* q = hb + i * 4608 + ((rp ^ wp) ? 18 : 0);
        xB[v] = comb(q[6], q[9], rp, wp);
      }
#pragma unroll
      for (int dk = 0; dk < 2; dk++)
#pragma unroll
        for (int s = 0; s < 4; s++) {
          int v0 = 2 * dk + 12 + (s & 1);
          float aa = 0.f, hh = 0.f;
#pragma unroll
          for (int j = 0; j < 7; j++) {
            float f = cF0[s][j];
            aa += f * xl[v0 - 2 * j];
            hh += f * xB[v0 - 2 * j];
          }
          a[4 * dk + s] = aa; hl[4 * dk + s] = hh;
        }
    }
    // ---- pass B: lh + hh streams (F1 taps); emit to smem ----
    {
      float xC[16], xD[16];
#pragma unroll
      for (int v = 0; v < 16; v++) {
        int p = pv[v];
        int i = p >> 1, rp = p & 1;
        const float* q = hb + i * 4608 + ((rp ^ wp) ? 18 : 0);
        xC[v] = comb(q[0], q[15], rp, wp);
        xD[v] = comb(q[3], q[12], rp, wp);
      }
#pragma unroll
      for (int dk = 0; dk < 2; dk++)
#pragma unroll
        for (int s = 0; s < 4; s++) {
          int v1 = 2 * dk + 13 - (s & 1);
          float lh = 0.f, hh = 0.f;
#pragma unroll
          for (int j = 0; j < 7; j++) {
            float f = cF1[s][j];
            lh += f * xC[v1 - 2 * j];
            hh += f * xD[v1 - 2 * j];
          }
          sY1[4 * dk + s][t] = a[4 * dk + s] + SCQ * lh;
          sY2[4 * dk + s][t] = SCQ * (hl[4 * dk + s] + hh);
        }
    }
  }
  __syncthreads();

  // ---- phase 2: horizontal qshift from smem -> g_Z ----
  int row = t >> 5, cp = t & 31;           // local k-group cp: 0..31
  float O[12];
#pragma unroll
  for (int i = 0; i < 12; i++) O[i] = 0.f;
#pragma unroll
  for (int s = 0; s < 4; s++) {
    int v0 = 2 * cp + 12 + (s & 1), v1 = 2 * cp + 13 - (s & 1);
#pragma unroll
    for (int j = 0; j < 7; j++) {
      float f0 = cF0[s][j], f1 = cF1[s][j];
#pragma unroll
      for (int c = 0; c < 3; c++) {
        O[s * 3 + c] += f0 * sY1[row][(v0 - 2 * j) * 3 + c]
                      + f1 * sY2[row][(v1 - 2 * j) * 3 + c];
      }
    }
  }
  int ob = ((b * 512 + 8 * kp + row) * 512 + 4 * (kw0 + cp)) * 3;
  float4* po = (float4*)(g_Z + ob);
#pragma unroll
  for (int m = 0; m < 3; m++)
    po[m] = make_float4(O[4 * m], O[4 * m + 1], O[4 * m + 2], O[4 * m + 3]);
}

// ---------------- kB: level-0 fused, tiled 8 rows x 64 cols (R8) ------------
__global__ __launch_bounds__(256) void kB_lvl0(const float* __restrict__ hi0,
                                               float* __restrict__ out) {
  __shared__ float sY1[8][210];
  __shared__ float sY2[8][210];
  int wt = blockIdx.x * 64;
  int rt = blockIdx.y * 8;
  int b  = blockIdx.z;
  int t  = threadIdx.x;

  if (t < 210) {
    int ucol = t / 3, c = t - 3 * ucol;
    int w  = wt - 3 + ucol;
    int wr = refl(w, 512);
    int jj = wr >> 1, wp = wr & 1;
    const float* zb = g_Z + ((b * 512) * 512 + wr) * 3 + c;
    const float* hb = hi0 + ((b * 256) * 256 + jj) * 36 + c;
    const bool vint = (rt >= 4 && rt <= 500);

    float a1[8], a2[8];
#pragma unroll
    for (int s = 0; s < 8; s++) { a1[s] = 0.f; a2[s] = 0.f; }

    {
      float xz[14], xhl[14];
#pragma unroll
      for (int v = 0; v < 14; v++) {
        int p = rt - 3 + v;
        int pr = vint ? p : refl(p, 512);
        xz[v] = zb[pr * 1536];
        int i = pr >> 1, rp = pr & 1;
        const float* qq = hb + i * 9216 + ((rp ^ wp) ? 18 : 0);
        xhl[v] = comb(qq[6], qq[9], rp, wp);
      }
#pragma unroll
      for (int s = 0; s < 8; s++)
#pragma unroll
        for (int j = 0; j < 7; j++) {
          float f = cG0[j];
          a1[s] += f * xz [s + 6 - j];
          a2[s] += f * xhl[s + 6 - j];
        }
    }
    {
      float xlh[12], xhh[12];
#pragma unroll
      for (int v = 0; v < 12; v++) {
        int p = rt - 2 + v;
        int pr = vint ? p : refl(p, 512);
        int i = pr >> 1, rp = pr & 1;
        const float* qq = hb + i * 9216 + ((rp ^ wp) ? 18 : 0);
        xlh[v] = comb(qq[0], qq[15], rp, wp);
        xhh[v] = comb(qq[3], qq[12], rp, wp);
      }
#pragma unroll
      for (int s = 0; s < 8; s++) {
        float lh = 0.f, hh = 0.f;
#pragma unroll
        for (int j = 0; j < 5; j++) {
          float f = cG1[j];
          lh += f * xlh[s + 4 - j];
          hh += f * xhh[s + 4 - j];
        }
        sY1[s][t] = a1[s] + SCQ * lh;
        sY2[s][t] = SCQ * (a2[s] + hh);
      }
    }
  }
  __syncthreads();

  int row = t >> 5, cp = t & 31;
  int cc0 = 2 * cp;
  float o[6];
#pragma unroll
  for (int d = 0; d < 2; d++) {
    int cc = cc0 + d;
#pragma unroll
    for (int c = 0; c < 3; c++) {
      float acc = 0.f;
#pragma unroll
      for (int j = 0; j < 7; j++) acc += cG0[j] * sY1[row][(cc + 6 - j) * 3 + c];
#pragma unroll
      for (int j = 0; j < 5; j++) acc += cG1[j] * sY2[row][(cc + 5 - j) * 3 + c];
      o[d * 3 + c] = acc;
    }
  }
  int ob = ((b * 512 + rt + row) * 512 + wt + cc0) * 3;
  float2* po = (float2*)(out + ob);
  po[0] = make_float2(o[0], o[1]);
  po[1] = make_float2(o[2], o[3]);
  po[2] = make_float2(o[4], o[5]);
}

extern "C" void kernel_launch(void* const* d_in, const int* in_sizes, int n_in,
                              void* d_out, int out_size) {
  const float *low = nullptr, *high0 = nullptr, *high1 = nullptr;
  for (int i = 0; i < n_in; i++) {
    if (in_sizes[i] == 8 * 256 * 256 * 3)       low   = (const float*)d_in[i];
    else if (in_sizes[i] == 8 * 256 * 256 * 36) high0 = (const float*)d_in[i];
    else if (in_sizes[i] == 8 * 128 * 128 * 36) high1 = (const float*)d_in[i];
  }
  float* out = (float*)d_out;

  kA_lvl1<<<dim3(4, 64, 8), 256>>>(low, high1);
  kB_lvl0<<<dim3(8, 64, 8), 256>>>(high0, out);
}